// round 8
// baseline (speedup 1.0000x reference)
#include <cuda_runtime.h>
#include <cuda_fp16.h>
#include <cstddef>

#define NMAX 100000
#define EMAX 1600000
#define FDIM 128

// ---------------- static scratch (no allocs allowed) ----------------
__device__ float    g_s[NMAX];            // row exp-sum (unnormalized)
__device__ float    g_rowsum[NMAX];       // rowsum of adj .* P (UNnormalized)
__device__ int      g_count[NMAX];        // row degree
__device__ int      g_off[NMAX + 1];      // CSR offsets
__device__ int      g_bsum[1024];         // scan block sums
__device__ float    g_feat1[NMAX];
__device__ float    g_feat2[NMAX];
__device__ float    g_ev[EMAX];           // exp(leaky(e)) per edge (COO order)
__device__ unsigned short g_rank[EMAX];   // within-row rank of each edge
__device__ int2     g_cu[EMAX];           // CSR interleaved (col, u-bits)
__device__ __half   g_xh[(size_t)NMAX * FDIM];   // fp16 copy of x
__device__ __half   g_hA[(size_t)NMAX * FDIM];   // fp16 update hop1
__device__ __half   g_hB[(size_t)NMAX * FDIM];   // fp16 update hop2

// ---------------- kernels ----------------

// feat1/feat2 dot products + fused x->fp16 conversion + per-row state init.
__global__ void k_feats(const float* __restrict__ x, const float* __restrict__ a, int n) {
    int gw = (blockIdx.x * blockDim.x + threadIdx.x) >> 5;
    int lane = threadIdx.x & 31;
    if (gw >= n) return;
    float4 v  = __ldg((const float4*)(x + (size_t)gw * FDIM) + lane);
    float4 a1 = __ldg((const float4*)a + lane);
    float4 a2 = __ldg((const float4*)(a + FDIM) + lane);

    __half2 h0 = __floats2half2_rn(v.x, v.y);
    __half2 h1 = __floats2half2_rn(v.z, v.w);
    uint2 packed;
    packed.x = *(unsigned*)&h0;
    packed.y = *(unsigned*)&h1;
    ((uint2*)g_xh)[(size_t)gw * 32 + lane] = packed;

    float d1 = v.x * a1.x + v.y * a1.y + v.z * a1.z + v.w * a1.w;
    float d2 = v.x * a2.x + v.y * a2.y + v.z * a2.z + v.w * a2.w;
    #pragma unroll
    for (int o = 16; o; o >>= 1) {
        d1 += __shfl_down_sync(0xffffffffu, d1, o);
        d2 += __shfl_down_sync(0xffffffffu, d2, o);
    }
    if (lane == 0) {
        g_feat1[gw] = d1; g_feat2[gw] = d2;
        g_s[gw] = 0.f; g_rowsum[gw] = 0.f; g_count[gw] = 0;
    }
}

// edge pass: exp(leaky(e)), row sum, degree+rank, UNnormalized rowsum
__global__ void k_edge1(const int* __restrict__ row, const int* __restrict__ col,
                        const float* __restrict__ adj, int e) {
    int j = blockIdx.x * blockDim.x + threadIdx.x;
    if (j >= e) return;
    int r = row[j];
    float ev = __ldg(&g_feat1[r]) + __ldg(&g_feat2[col[j]]);
    ev = (ev >= 0.f) ? ev : 0.2f * ev;
    float ex = __expf(ev);
    g_ev[j] = ex;
    atomicAdd(&g_s[r], ex);
    atomicAdd(&g_rowsum[r], 0.5f * adj[j] * ex);
    int rank = atomicAdd(&g_count[r], 1);
    g_rank[j] = (unsigned short)rank;
}

// scan 1: per-1024-block exclusive scan of degrees; block totals in g_bsum
__global__ void k_scan1(int n) {
    __shared__ int sh[1024];
    int i = blockIdx.x * 1024 + threadIdx.x;
    int v = (i < n) ? g_count[i] : 0;
    sh[threadIdx.x] = v;
    __syncthreads();
    #pragma unroll
    for (int o = 1; o < 1024; o <<= 1) {
        int t = (threadIdx.x >= o) ? sh[threadIdx.x - o] : 0;
        __syncthreads();
        sh[threadIdx.x] += t;
        __syncthreads();
    }
    if (i < n) g_off[i] = sh[threadIdx.x] - v;
    if (threadIdx.x == 1023) g_bsum[blockIdx.x] = sh[1023];
}

// scan 2+3 fused
__global__ void k_scan23(int nb, int n) {
    __shared__ int s_prefix;
    int b = blockIdx.x;
    if (threadIdx.x < 32) {
        int acc = 0;
        for (int i = threadIdx.x; i < b; i += 32) acc += g_bsum[i];
        #pragma unroll
        for (int o = 16; o; o >>= 1) acc += __shfl_down_sync(0xffffffffu, acc, o);
        if (threadIdx.x == 0) s_prefix = acc;
    }
    __syncthreads();
    int prefix = s_prefix;
    int i = b * 1024 + threadIdx.x;
    if (i < n) g_off[i] += prefix;
    if (b == nb - 1 && threadIdx.x == 0) g_off[n] = prefix + g_bsum[nb - 1];
}

// scatter: normalized u into interleaved CSR. No atomics.
__global__ void k_scatter(const int* __restrict__ row, const int* __restrict__ col, int e) {
    int j = blockIdx.x * blockDim.x + threadIdx.x;
    if (j >= e) return;
    int r = row[j];
    float u = g_ev[j] / __ldg(&g_s[r]);
    int pos = __ldg(&g_off[r]) + (int)g_rank[j];
    int2 cu;
    cu.x = col[j];
    cu.y = __float_as_int(u);
    g_cu[pos] = cu;
}

// fused SpMM, fp16 operands, fp32 accumulation. TWO rows per warp:
// lanes 0-15 = row 2w, lanes 16-31 = row 2w+1; each lane owns 8 features (uint4).
__global__ void __launch_bounds__(256) k_spmm(const float* __restrict__ x,
                                              float* __restrict__ out,
                                              const float* __restrict__ cheb,
                                              int step, int n) {
    int warp = (blockIdx.x * blockDim.x + threadIdx.x) >> 5;
    int lane = threadIdx.x & 31;
    int half = lane >> 4;       // 0 or 1
    int hl   = lane & 15;       // lane within half
    int r = 2 * warp + half;
    bool rv = (r < n);

    const uint4* in_upd = (const uint4*)((step == 0) ? g_xh : ((step == 1) ? g_hA : g_hB));

    int beg = rv ? __ldg(&g_off[r]) : 0;
    int end = rv ? __ldg(&g_off[r + 1]) : 0;
    int deg = end - beg;
    int degO = __shfl_xor_sync(0xffffffffu, deg, 16);
    int degW = max(deg, degO);

    float4 a0 = make_float4(0.f, 0.f, 0.f, 0.f);
    float4 a1 = make_float4(0.f, 0.f, 0.f, 0.f);

    for (int j0 = 0; j0 < degW; j0 += 16) {
        int2 cu = make_int2(0, 0);
        if (j0 + hl < deg) cu = __ldg(&g_cu[beg + j0 + hl]);
        int mW = min(16, degW - j0);
        #pragma unroll 4
        for (int t = 0; t < mW; t++) {
            int src = (half << 4) + t;
            int   cc = __shfl_sync(0xffffffffu, cu.x, src);
            float uu = __int_as_float(__shfl_sync(0xffffffffu, cu.y, src));
            if (j0 + t < deg) {                       // this half still has edges
                uint4 raw = __ldg(in_upd + (size_t)cc * 16 + hl);
                float2 f0 = __half22float2(*(__half2*)&raw.x);
                float2 f1 = __half22float2(*(__half2*)&raw.y);
                float2 f2 = __half22float2(*(__half2*)&raw.z);
                float2 f3 = __half22float2(*(__half2*)&raw.w);
                a0.x += uu * f0.x;  a0.y += uu * f0.y;
                a0.z += uu * f1.x;  a0.w += uu * f1.y;
                a1.x += uu * f2.x;  a1.y += uu * f2.y;
                a1.z += uu * f3.x;  a1.w += uu * f3.y;
            }
        }
    }

    if (!rv) return;

    if (step < 2) {
        __half2 h0 = __floats2half2_rn(a0.x, a0.y);
        __half2 h1 = __floats2half2_rn(a0.z, a0.w);
        __half2 h2 = __floats2half2_rn(a1.x, a1.y);
        __half2 h3 = __floats2half2_rn(a1.z, a1.w);
        uint4 packed;
        packed.x = *(unsigned*)&h0;
        packed.y = *(unsigned*)&h1;
        packed.z = *(unsigned*)&h2;
        packed.w = *(unsigned*)&h3;
        ((uint4*)(step == 0 ? g_hA : g_hB))[(size_t)r * 16 + hl] = packed;
    } else {
        float s = __ldg(&g_s[r]);
        float inv_s = (s > 0.f) ? 1.f / s : 0.f;
        float rs0 = __ldg(&g_rowsum[r]) * inv_s;
        float c0 = 1.f / (1.f + __expf(-__ldg(&cheb[0])));
        float c1 = 1.f / (1.f + __expf(-__ldg(&cheb[1])));
        float rs1 = rs0 * c0;
        float rs2 = rs1 * c1;
        float w0 = 0.009f * (1.f - 0.9f * rs0);
        float w1 = 0.09f  * (1.f - 0.9f * rs1);
        float w2 = 0.9f   * (1.f - 0.9f * rs2);

        size_t v4base = (size_t)r * 32 + 2 * hl;          // float4 index into 128-f rows
        float4 xv0 = __ldg((const float4*)x + v4base);
        float4 xv1 = __ldg((const float4*)x + v4base + 1);
        uint4 rawa = ((const uint4*)g_hA)[(size_t)r * 16 + hl];
        uint4 rawb = ((const uint4*)g_hB)[(size_t)r * 16 + hl];
        float2 pa0 = __half22float2(*(__half2*)&rawa.x);
        float2 pa1 = __half22float2(*(__half2*)&rawa.y);
        float2 pa2 = __half22float2(*(__half2*)&rawa.z);
        float2 pa3 = __half22float2(*(__half2*)&rawa.w);
        float2 pb0 = __half22float2(*(__half2*)&rawb.x);
        float2 pb1 = __half22float2(*(__half2*)&rawb.y);
        float2 pb2 = __half22float2(*(__half2*)&rawb.z);
        float2 pb3 = __half22float2(*(__half2*)&rawb.w);

        float4 o0, o1;
        o0.x = 0.001f * xv0.x + w0 * pa0.x + w1 * pb0.x + w2 * a0.x;
        o0.y = 0.001f * xv0.y + w0 * pa0.y + w1 * pb0.y + w2 * a0.y;
        o0.z = 0.001f * xv0.z + w0 * pa1.x + w1 * pb1.x + w2 * a0.z;
        o0.w = 0.001f * xv0.w + w0 * pa1.y + w1 * pb1.y + w2 * a0.w;
        o1.x = 0.001f * xv1.x + w0 * pa2.x + w1 * pb2.x + w2 * a1.x;
        o1.y = 0.001f * xv1.y + w0 * pa2.y + w1 * pb2.y + w2 * a1.y;
        o1.z = 0.001f * xv1.z + w0 * pa3.x + w1 * pb3.x + w2 * a1.z;
        o1.w = 0.001f * xv1.w + w0 * pa3.y + w1 * pb3.y + w2 * a1.w;
        ((float4*)out)[v4base]     = o0;
        ((float4*)out)[v4base + 1] = o1;
    }
}

// ---------------- launch ----------------
extern "C" void kernel_launch(void* const* d_in, const int* in_sizes, int n_in,
                              void* d_out, int out_size) {
    const float* x    = (const float*)d_in[0];
    const float* a    = (const float*)d_in[2];
    const float* cheb = (const float*)d_in[4];
    const float* adj  = (const float*)d_in[5];
    const int*   row  = (const int*)d_in[6];
    const int*   col  = (const int*)d_in[7];
    float* out = (float*)d_out;

    int n = in_sizes[0] / FDIM;
    int e = in_sizes[5];

    k_feats<<<((size_t)n * 32 + 255) / 256, 256>>>(x, a, n);
    k_edge1<<<(e + 255) / 256, 256>>>(row, col, adj, e);

    int nb = (n + 1023) / 1024;
    k_scan1<<<nb, 1024>>>(n);
    k_scan23<<<nb, 1024>>>(nb, n);

    k_scatter<<<(e + 255) / 256, 256>>>(row, col, e);

    // 8 warps per block, 2 rows per warp -> 16 rows per block
    int spmm_blocks = (n + 15) / 16;
    for (int step = 0; step < 3; step++)
        k_spmm<<<spmm_blocks, 256>>>(x, out, cheb, step, n);
}

// round 9
// speedup vs baseline: 1.0690x; 1.0690x over previous
#include <cuda_runtime.h>
#include <cuda_fp16.h>
#include <cstddef>

#define NMAX 100000
#define EMAX 1600000
#define FDIM 128

// ---------------- static scratch (no allocs allowed) ----------------
__device__ float    g_s[NMAX];            // row exp-sum (unnormalized)
__device__ float    g_rowsum[NMAX];       // rowsum of adj .* P (UNnormalized)
__device__ int      g_count[NMAX];        // row degree
__device__ int      g_off[NMAX + 1];      // CSR offsets
__device__ int      g_bsum[1024];         // scan block sums
__device__ float    g_feat1[NMAX];
__device__ float    g_feat2[NMAX];
__device__ float    g_ev[EMAX];           // exp(leaky(e)) per edge (COO order)
__device__ unsigned short g_rank[EMAX];   // within-row rank of each edge
__device__ int2     g_cu[EMAX];           // CSR interleaved (col, u-bits)
__device__ __half   g_xh[(size_t)NMAX * FDIM];   // fp16 copy of x
__device__ __half   g_hA[(size_t)NMAX * FDIM];   // fp16 update hop1
__device__ __half   g_hB[(size_t)NMAX * FDIM];   // fp16 update hop2

// ---------------- kernels ----------------

// feat1/feat2 dot products + fused x->fp16 conversion + per-row state init.
__global__ void k_feats(const float* __restrict__ x, const float* __restrict__ a, int n) {
    int gw = (blockIdx.x * blockDim.x + threadIdx.x) >> 5;
    int lane = threadIdx.x & 31;
    if (gw >= n) return;
    float4 v  = __ldg((const float4*)(x + (size_t)gw * FDIM) + lane);
    float4 a1 = __ldg((const float4*)a + lane);
    float4 a2 = __ldg((const float4*)(a + FDIM) + lane);

    __half2 h0 = __floats2half2_rn(v.x, v.y);
    __half2 h1 = __floats2half2_rn(v.z, v.w);
    uint2 packed;
    packed.x = *(unsigned*)&h0;
    packed.y = *(unsigned*)&h1;
    ((uint2*)g_xh)[(size_t)gw * 32 + lane] = packed;

    float d1 = v.x * a1.x + v.y * a1.y + v.z * a1.z + v.w * a1.w;
    float d2 = v.x * a2.x + v.y * a2.y + v.z * a2.z + v.w * a2.w;
    #pragma unroll
    for (int o = 16; o; o >>= 1) {
        d1 += __shfl_down_sync(0xffffffffu, d1, o);
        d2 += __shfl_down_sync(0xffffffffu, d2, o);
    }
    if (lane == 0) {
        g_feat1[gw] = d1; g_feat2[gw] = d2;
        g_s[gw] = 0.f; g_rowsum[gw] = 0.f; g_count[gw] = 0;
    }
}

// edge pass: exp(leaky(e)), row sum, degree+rank, UNnormalized rowsum
__global__ void k_edge1(const int* __restrict__ row, const int* __restrict__ col,
                        const float* __restrict__ adj, int e) {
    int j = blockIdx.x * blockDim.x + threadIdx.x;
    if (j >= e) return;
    int r = row[j];
    float ev = __ldg(&g_feat1[r]) + __ldg(&g_feat2[col[j]]);
    ev = (ev >= 0.f) ? ev : 0.2f * ev;
    float ex = __expf(ev);
    g_ev[j] = ex;
    atomicAdd(&g_s[r], ex);
    atomicAdd(&g_rowsum[r], 0.5f * adj[j] * ex);
    int rank = atomicAdd(&g_count[r], 1);
    g_rank[j] = (unsigned short)rank;
}

// scan 1: warp-shuffle per-1024-block exclusive scan of degrees
__global__ void k_scan1(int n) {
    __shared__ int warp_tot[32];
    int i = blockIdx.x * 1024 + threadIdx.x;
    int lane = threadIdx.x & 31, wid = threadIdx.x >> 5;
    int v = (i < n) ? g_count[i] : 0;
    int s = v;
    #pragma unroll
    for (int o = 1; o < 32; o <<= 1) {
        int t = __shfl_up_sync(0xffffffffu, s, o);
        if (lane >= o) s += t;
    }
    if (lane == 31) warp_tot[wid] = s;
    __syncthreads();
    if (wid == 0) {
        int w = warp_tot[lane];
        #pragma unroll
        for (int o = 1; o < 32; o <<= 1) {
            int t = __shfl_up_sync(0xffffffffu, w, o);
            if (lane >= o) w += t;
        }
        warp_tot[lane] = w;
    }
    __syncthreads();
    int base = wid ? warp_tot[wid - 1] : 0;
    if (i < n) g_off[i] = base + s - v;            // exclusive
    if (threadIdx.x == 1023) g_bsum[blockIdx.x] = base + s;
}

// scan 2+3 fused
__global__ void k_scan23(int nb, int n) {
    __shared__ int s_prefix;
    int b = blockIdx.x;
    if (threadIdx.x < 32) {
        int acc = 0;
        for (int i = threadIdx.x; i < b; i += 32) acc += g_bsum[i];
        #pragma unroll
        for (int o = 16; o; o >>= 1) acc += __shfl_down_sync(0xffffffffu, acc, o);
        if (threadIdx.x == 0) s_prefix = acc;
    }
    __syncthreads();
    int prefix = s_prefix;
    int i = b * 1024 + threadIdx.x;
    if (i < n) g_off[i] += prefix;
    if (b == nb - 1 && threadIdx.x == 0) g_off[n] = prefix + g_bsum[nb - 1];
}

// scatter: normalized u into interleaved CSR. No atomics.
__global__ void k_scatter(const int* __restrict__ row, const int* __restrict__ col, int e) {
    int j = blockIdx.x * blockDim.x + threadIdx.x;
    if (j >= e) return;
    int r = row[j];
    float u = g_ev[j] / __ldg(&g_s[r]);
    int pos = __ldg(&g_off[r]) + (int)g_rank[j];
    int2 cu;
    cu.x = col[j];
    cu.y = __float_as_int(u);
    g_cu[pos] = cu;
}

// fused SpMM, fp16 gather operands, fp32 accumulation. One WARP per row.
// (Round-7 proven configuration: uint2 per lane, shfl broadcast, unroll 8.)
__global__ void __launch_bounds__(256) k_spmm(const float* __restrict__ x,
                                              float* __restrict__ out,
                                              const float* __restrict__ cheb,
                                              int step, int n) {
    int warp = (blockIdx.x * blockDim.x + threadIdx.x) >> 5;
    int lane = threadIdx.x & 31;
    if (warp >= n) return;
    int r = warp;

    const uint2* in_upd = (const uint2*)((step == 0) ? g_xh : ((step == 1) ? g_hA : g_hB));

    int beg = __ldg(&g_off[r]), end = __ldg(&g_off[r + 1]);

    float4 acc = make_float4(0.f, 0.f, 0.f, 0.f);

    for (int j0 = beg; j0 < end; j0 += 32) {
        int k = j0 + lane;
        int2 cu = make_int2(0, 0);
        if (k < end) cu = __ldg(&g_cu[k]);
        int m = min(32, end - j0);
        #pragma unroll 8
        for (int t = 0; t < m; t++) {
            int   cc = __shfl_sync(0xffffffffu, cu.x, t);
            float uu = __int_as_float(__shfl_sync(0xffffffffu, cu.y, t));
            uint2 raw = __ldg(in_upd + (size_t)cc * 32 + lane);
            float2 f0 = __half22float2(*(__half2*)&raw.x);
            float2 f1 = __half22float2(*(__half2*)&raw.y);
            acc.x += uu * f0.x;
            acc.y += uu * f0.y;
            acc.z += uu * f1.x;
            acc.w += uu * f1.y;
        }
    }

    size_t v2idx = (size_t)r * 32 + lane;
    if (step < 2) {
        __half2 h0 = __floats2half2_rn(acc.x, acc.y);
        __half2 h1 = __floats2half2_rn(acc.z, acc.w);
        uint2 packed;
        packed.x = *(unsigned*)&h0;
        packed.y = *(unsigned*)&h1;
        ((uint2*)(step == 0 ? g_hA : g_hB))[v2idx] = packed;
    } else {
        float rs0 = __ldg(&g_rowsum[r]) * ((__ldg(&g_s[r]) > 0.f) ? 1.f / __ldg(&g_s[r]) : 0.f);
        float c0 = 1.f / (1.f + __expf(-__ldg(&cheb[0])));
        float c1 = 1.f / (1.f + __expf(-__ldg(&cheb[1])));
        float rs1 = rs0 * c0;
        float rs2 = rs1 * c1;
        float w0 = 0.009f * (1.f - 0.9f * rs0);
        float w1 = 0.09f  * (1.f - 0.9f * rs1);
        float w2 = 0.9f   * (1.f - 0.9f * rs2);

        uint2 rawx = ((const uint2*)g_xh)[v2idx];
        uint2 rawa = ((const uint2*)g_hA)[v2idx];
        uint2 rawb = ((const uint2*)g_hB)[v2idx];
        float2 x0 = __half22float2(*(__half2*)&rawx.x);
        float2 x1 = __half22float2(*(__half2*)&rawx.y);
        float2 a0 = __half22float2(*(__half2*)&rawa.x);
        float2 a1 = __half22float2(*(__half2*)&rawa.y);
        float2 b0 = __half22float2(*(__half2*)&rawb.x);
        float2 b1 = __half22float2(*(__half2*)&rawb.y);
        float4 o;
        o.x = 0.001f * x0.x + w0 * a0.x + w1 * b0.x + w2 * acc.x;
        o.y = 0.001f * x0.y + w0 * a0.y + w1 * b0.y + w2 * acc.y;
        o.z = 0.001f * x1.x + w0 * a1.x + w1 * b1.x + w2 * acc.z;
        o.w = 0.001f * x1.y + w0 * a1.y + w1 * b1.y + w2 * acc.w;
        ((float4*)out)[(size_t)r * (FDIM / 4) + lane] = o;
    }
}

// ---------------- launch ----------------
extern "C" void kernel_launch(void* const* d_in, const int* in_sizes, int n_in,
                              void* d_out, int out_size) {
    const float* x    = (const float*)d_in[0];
    const float* a    = (const float*)d_in[2];
    const float* cheb = (const float*)d_in[4];
    const float* adj  = (const float*)d_in[5];
    const int*   row  = (const int*)d_in[6];
    const int*   col  = (const int*)d_in[7];
    float* out = (float*)d_out;

    int n = in_sizes[0] / FDIM;
    int e = in_sizes[5];

    k_feats<<<((size_t)n * 32 + 255) / 256, 256>>>(x, a, n);
    k_edge1<<<(e + 255) / 256, 256>>>(row, col, adj, e);

    int nb = (n + 1023) / 1024;
    k_scan1<<<nb, 1024>>>(n);
    k_scan23<<<nb, 1024>>>(nb, n);

    k_scatter<<<(e + 255) / 256, 256>>>(row, col, e);

    int spmm_blocks = (n + 7) / 8;
    for (int step = 0; step < 3; step++)
        k_spmm<<<spmm_blocks, 256>>>(x, out, cheb, step, n);
}